// round 6
// baseline (speedup 1.0000x reference)
#include <cuda_runtime.h>
#include <math.h>

#define B_SZ   2
#define HEADS  8
#define S_LEN  2048
#define DM     512
#define HD     64
#define NRPR   513
#define NRPR_PAD 520
#define BH     16   // B_SZ*HEADS

typedef unsigned long long ull;

// ---------------- scratch (device globals) ----------------
__device__ float g_Qh[BH * S_LEN * HD];        //  8 MB
__device__ float g_Kh[BH * S_LEN * HD];        //  8 MB
__device__ float g_Vh[BH * S_LEN * HD];        //  8 MB
__device__ float g_P [BH * S_LEN * NRPR_PAD];  // 68 MB
__device__ float g_SC[BH * S_LEN * HD];        //  8 MB
__device__ float g_sum[BH * S_LEN];            // row sums of exp
__device__ float g_lo [BH * S_LEN];            // sum over j-i <= -256
__device__ float g_hi [BH * S_LEN];            // sum over j-i >= 256

// ---------------- f32x2 helpers ----------------
__device__ __forceinline__ void ffma2(ull& d, ull a, ull b) {
  asm("fma.rn.f32x2 %0, %1, %2, %0;" : "+l"(d) : "l"(a), "l"(b));
}
__device__ __forceinline__ ull pack2(float x) {
  ull r; unsigned u = __float_as_uint(x);
  asm("mov.b64 %0, {%1, %1};" : "=l"(r) : "r"(u));
  return r;
}
__device__ __forceinline__ float2 unpack2(ull v) {
  unsigned lo, hi;
  asm("mov.b64 {%0, %1}, %2;" : "=r"(lo), "=r"(hi) : "l"(v));
  return make_float2(__uint_as_float(lo), __uint_as_float(hi));
}
__device__ __forceinline__ float red16(float v) {
#pragma unroll
  for (int o = 8; o > 0; o >>= 1) v += __shfl_xor_sync(~0u, v, o);
  return v;
}

// 8x8 micro step: acc2[ip][j] accumulates rows (ty*8+2ip, +1) x col tx*8+j
template <int BK, int LDA, int LDB>
__device__ __forceinline__ void mm8x8(const float (*As)[LDA], const float (*Bs)[LDB],
                                      ull acc2[4][8], int tx, int ty) {
#pragma unroll
  for (int k = 0; k < BK; k++) {
    ulonglong2 a01 = *(const ulonglong2*)&As[k][ty * 8];
    ulonglong2 a23 = *(const ulonglong2*)&As[k][ty * 8 + 4];
    float4 b0 = *(const float4*)&Bs[k][tx * 8];
    float4 b1 = *(const float4*)&Bs[k][tx * 8 + 4];
    ull A2[4] = {a01.x, a01.y, a23.x, a23.y};
    ull bd[8] = {pack2(b0.x), pack2(b0.y), pack2(b0.z), pack2(b0.w),
                 pack2(b1.x), pack2(b1.y), pack2(b1.z), pack2(b1.w)};
#pragma unroll
    for (int ip = 0; ip < 4; ip++)
#pragma unroll
      for (int j = 0; j < 8; j++) ffma2(acc2[ip][j], A2[ip], bd[j]);
  }
}

// 8x4 micro step (av): acc2[ip][j], cols tx*4+j
template <int BK, int LDA, int LDB>
__device__ __forceinline__ void mm8x4(const float (*As)[LDA], const float (*Bs)[LDB],
                                      ull acc2[4][4], int tx, int ty) {
#pragma unroll
  for (int k = 0; k < BK; k++) {
    ulonglong2 a01 = *(const ulonglong2*)&As[k][ty * 8];
    ulonglong2 a23 = *(const ulonglong2*)&As[k][ty * 8 + 4];
    float4 b = *(const float4*)&Bs[k][tx * 4];
    ull A2[4] = {a01.x, a01.y, a23.x, a23.y};
    ull bd[4] = {pack2(b.x), pack2(b.y), pack2(b.z), pack2(b.w)};
#pragma unroll
    for (int ip = 0; ip < 4; ip++)
#pragma unroll
      for (int j = 0; j < 4; j++) ffma2(acc2[ip][j], A2[ip], bd[j]);
  }
}

// =====================================================================
// K0: zero accumulators
// =====================================================================
__global__ void zero_kernel() {
  int t = blockIdx.x * 1024 + threadIdx.x;
  if (t < BH * S_LEN) g_sum[t] = 0.f;
  else if (t < 2 * BH * S_LEN) g_lo[t - BH * S_LEN] = 0.f;
  else g_hi[t - 2 * BH * S_LEN] = 0.f;
}

// =====================================================================
// K1: projections -> head layout. 128x128 tile, BK=16, 8x8 micro f32x2
// =====================================================================
__global__ void __launch_bounds__(256, 2) proj_kernel(
    const float* __restrict__ query, const float* __restrict__ value,
    const float* __restrict__ Wq, const float* __restrict__ Wk,
    const float* __restrict__ Wv) {
  const int which = blockIdx.z;
  const float* A = (which == 0) ? query : value;
  const float* W = (which == 0) ? Wq : (which == 1) ? Wk : Wv;
  float* outp    = (which == 0) ? g_Qh : (which == 1) ? g_Kh : g_Vh;

  __shared__ __align__(16) float As[16][132];
  __shared__ __align__(16) float Bs[16][132];
  const int tid = threadIdx.x;
  const int tx = tid & 15, ty = tid >> 4;
  const int m0 = blockIdx.y * 128;
  const int n0 = blockIdx.x * 128;

  ull acc2[4][8];
#pragma unroll
  for (int i = 0; i < 4; i++)
#pragma unroll
    for (int j = 0; j < 8; j++) acc2[i][j] = 0ull;

  for (int k0 = 0; k0 < DM; k0 += 16) {
#pragma unroll
    for (int l = 0; l < 2; l++) {
      int idx = tid + 256 * l;
      int row = idx >> 2, c4 = (idx & 3) << 2;
      float4 v = *(const float4*)(A + (size_t)(m0 + row) * DM + k0 + c4);
      As[c4 + 0][row] = v.x; As[c4 + 1][row] = v.y;
      As[c4 + 2][row] = v.z; As[c4 + 3][row] = v.w;
      int br = idx >> 5, bc = (idx & 31) << 2;
      *(float4*)&Bs[br][bc] = *(const float4*)(W + (size_t)(k0 + br) * DM + n0 + bc);
    }
    __syncthreads();
    mm8x8<16, 132, 132>(As, Bs, acc2, tx, ty);
    __syncthreads();
  }
#pragma unroll
  for (int ip = 0; ip < 4; ip++) {
    float2 f[8];
#pragma unroll
    for (int j = 0; j < 8; j++) f[j] = unpack2(acc2[ip][j]);
#pragma unroll
    for (int rr = 0; rr < 2; rr++) {
      int row = m0 + ty * 8 + ip * 2 + rr;
      int b = row >> 11, s = row & (S_LEN - 1);
      int col = n0 + tx * 8;
      int h = col >> 6, d0 = col & 63;
      float* dst = outp + (((size_t)(b * HEADS + h)) * S_LEN + s) * HD + d0;
      float o[8];
#pragma unroll
      for (int j = 0; j < 8; j++) o[j] = rr ? f[j].y : f[j].x;
      *(float4*)&dst[0] = make_float4(o[0], o[1], o[2], o[3]);
      *(float4*)&dst[4] = make_float4(o[4], o[5], o[6], o[7]);
    }
  }
}

// =====================================================================
// K2: P[bh,i,r] = Q . Ek^T   (M=2048, N=513 padded, K=64)
// =====================================================================
__global__ void __launch_bounds__(256, 2) p_kernel(const float* __restrict__ Ek) {
  const int bh = blockIdx.z;
  const int i0 = blockIdx.y * 128;
  const int n0 = blockIdx.x * 128;
  __shared__ __align__(16) float As[16][132];
  __shared__ __align__(16) float Bs[16][132];
  const int tid = threadIdx.x;
  const int tx = tid & 15, ty = tid >> 4;
  const float* Qb = g_Qh + (size_t)bh * S_LEN * HD;

  ull acc2[4][8];
#pragma unroll
  for (int i = 0; i < 4; i++)
#pragma unroll
    for (int j = 0; j < 8; j++) acc2[i][j] = 0ull;

  for (int k0 = 0; k0 < HD; k0 += 16) {
#pragma unroll
    for (int l = 0; l < 2; l++) {
      int idx = tid + 256 * l;
      int row = idx >> 2, c4 = (idx & 3) << 2;
      float4 v = *(const float4*)(Qb + (size_t)(i0 + row) * HD + k0 + c4);
      As[c4 + 0][row] = v.x; As[c4 + 1][row] = v.y;
      As[c4 + 2][row] = v.z; As[c4 + 3][row] = v.w;
      float4 w = make_float4(0.f, 0.f, 0.f, 0.f);
      if (n0 + row < NRPR)
        w = *(const float4*)(Ek + (size_t)(n0 + row) * HD + k0 + c4);
      Bs[c4 + 0][row] = w.x; Bs[c4 + 1][row] = w.y;
      Bs[c4 + 2][row] = w.z; Bs[c4 + 3][row] = w.w;
    }
    __syncthreads();
    mm8x8<16, 132, 132>(As, Bs, acc2, tx, ty);
    __syncthreads();
  }
#pragma unroll
  for (int ip = 0; ip < 4; ip++) {
    float2 f[8];
#pragma unroll
    for (int j = 0; j < 8; j++) f[j] = unpack2(acc2[ip][j]);
#pragma unroll
    for (int rr = 0; rr < 2; rr++) {
      int i = i0 + ty * 8 + ip * 2 + rr;
      float* dst = g_P + ((size_t)bh * S_LEN + i) * NRPR_PAD;
#pragma unroll
      for (int j = 0; j < 8; j++) {
        int r = n0 + tx * 8 + j;
        if (r < NRPR) dst[r] = rr ? f[j].y : f[j].x;
      }
    }
  }
}

// =====================================================================
// K3: E[bh,i,j] = exp((q.k + P[clip(j-i)])/8); row sum/lo/hi atomics
// 128x128 tile, K=64 (BK=32 x2), 8x8 micro f32x2
// =====================================================================
__global__ void __launch_bounds__(256, 2) alpha_kernel(float* __restrict__ attn) {
  const int bh = blockIdx.z;
  const int i0 = blockIdx.y * 128;
  const int j0 = blockIdx.x * 128;
  __shared__ __align__(16) float Qs[32][132];
  __shared__ __align__(16) float Ks[32][132];
  const int tid = threadIdx.x;
  const int tx = tid & 15, ty = tid >> 4;
  const float* Qb = g_Qh + (size_t)bh * S_LEN * HD;
  const float* Kb = g_Kh + (size_t)bh * S_LEN * HD;
  const int bhS = bh * S_LEN;

  ull acc2[4][8];
#pragma unroll
  for (int i = 0; i < 4; i++)
#pragma unroll
    for (int j = 0; j < 8; j++) acc2[i][j] = 0ull;

  for (int k0 = 0; k0 < HD; k0 += 32) {
#pragma unroll
    for (int l = 0; l < 4; l++) {
      int idx = tid + 256 * l;
      int row = idx >> 3, c4 = (idx & 7) << 2;
      float4 v = *(const float4*)(Qb + (size_t)(i0 + row) * HD + k0 + c4);
      Qs[c4 + 0][row] = v.x; Qs[c4 + 1][row] = v.y;
      Qs[c4 + 2][row] = v.z; Qs[c4 + 3][row] = v.w;
      float4 w = *(const float4*)(Kb + (size_t)(j0 + row) * HD + k0 + c4);
      Ks[c4 + 0][row] = w.x; Ks[c4 + 1][row] = w.y;
      Ks[c4 + 2][row] = w.z; Ks[c4 + 3][row] = w.w;
    }
    __syncthreads();
    mm8x8<32, 132, 132>(Qs, Ks, acc2, tx, ty);
    __syncthreads();
  }

  // tile class: 0 middle-pure, 1 lo-pure, 2 hi-pure, 3 mixed (diff = +-256)
  int mode;
  {
    int diff = j0 - i0;
    if (diff >= -128 && diff <= 128) mode = 0;
    else if (diff <= -384) mode = 1;
    else if (diff >= 384) mode = 2;
    else mode = 3;
  }

#pragma unroll
  for (int ip = 0; ip < 4; ip++) {
    float2 f[8];
#pragma unroll
    for (int j = 0; j < 8; j++) f[j] = unpack2(acc2[ip][j]);
#pragma unroll
    for (int rr = 0; rr < 2; rr++) {
      int i = i0 + ty * 8 + ip * 2 + rr;
      const float* Prow = g_P + (size_t)(bhS + i) * NRPR_PAD + 256;
      float v[8], sA = 0.f, sL = 0.f, sH = 0.f;
#pragma unroll
      for (int j8 = 0; j8 < 8; j8++) {
        int j = j0 + tx * 8 + j8;
        int rel = j - i;
        int relc = rel < -256 ? -256 : (rel > 256 ? 256 : rel);
        float raw = rr ? f[j8].y : f[j8].x;
        float e = __expf((raw + Prow[relc]) * 0.125f);
        v[j8] = e;
        sA += e;
        if (mode == 3) {
          if (rel <= -256) sL += e;
          else if (rel >= 256) sH += e;
        }
      }
      float* orow = attn + (size_t)(bhS + i) * S_LEN + j0 + tx * 8;
      *(float4*)&orow[0] = make_float4(v[0], v[1], v[2], v[3]);
      *(float4*)&orow[4] = make_float4(v[4], v[5], v[6], v[7]);

      float rA = red16(sA);
      if (mode == 3) { sL = red16(sL); sH = red16(sH); }
      if (tx == 0) {
        atomicAdd(&g_sum[bhS + i], rA);
        if (mode == 1) atomicAdd(&g_lo[bhS + i], rA);
        else if (mode == 2) atomicAdd(&g_hi[bhS + i], rA);
        else if (mode == 3) {
          atomicAdd(&g_lo[bhS + i], sL);
          atomicAdd(&g_hi[bhS + i], sH);
        }
      }
    }
  }
}

// =====================================================================
// K4: scores = (E@V + band(E)@Ev + lo*Ev0 + hi*Ev512) / sum
//     also writes normalized attn back to d_out.
// per block: 128 i-rows x N=64, K sweep 2048 + 512-wide band
// =====================================================================
__global__ void __launch_bounds__(256, 2) av_kernel(float* __restrict__ attn,
                                                    const float* __restrict__ Ev) {
  const int bh = blockIdx.y;
  const int i0 = blockIdx.x * 128;
  __shared__ __align__(16) float As[32][132];
  __shared__ __align__(16) float Bs[32][68];
  __shared__ float invs[128], los[128], his[128];
  const int tid = threadIdx.x;
  const int tx = tid & 15, ty = tid >> 4;
  const int bhS = bh * S_LEN;
  const float* Vb = g_Vh + (size_t)bh * S_LEN * HD;

  if (tid < 128) {
    int g = bhS + i0 + tid;
    invs[tid] = 1.0f / g_sum[g];
    los[tid] = g_lo[g];
    his[tid] = g_hi[g];
  }
  __syncthreads();

  ull acc2[4][4];
#pragma unroll
  for (int i = 0; i < 4; i++)
#pragma unroll
    for (int j = 0; j < 4; j++) acc2[i][j] = 0ull;

  // ---- rel band phase: A[i][r] = E[i, i+r-256] (r=1..511), B = Ev[r] ----
  // NOTE: per-row j offset is NOT 16B-aligned -> scalar loads only.
  for (int r0 = 0; r0 < 512; r0 += 32) {
#pragma unroll
    for (int l = 0; l < 4; l++) {
      int idx = tid + 256 * l;
      int row = idx >> 3, c4 = (idx & 7) << 2;
      int i = i0 + row;
      int j = i + r0 + c4 - 256;
      const float* Erow = attn + (size_t)(bhS + i) * S_LEN;
      float t[4];
#pragma unroll
      for (int e = 0; e < 4; e++) {
        int r = r0 + c4 + e, jj = j + e;
        t[e] = (r >= 1 && jj >= 0 && jj < S_LEN) ? Erow[jj] : 0.f;
      }
      As[c4 + 0][row] = t[0]; As[c4 + 1][row] = t[1];
      As[c4 + 2][row] = t[2]; As[c4 + 3][row] = t[3];
    }
#pragma unroll
    for (int l = 0; l < 2; l++) {
      int idx = tid + 256 * l;
      int row = idx >> 4, c4 = (idx & 15) << 2;
      *(float4*)&Bs[row][c4] = *(const float4*)(Ev + (size_t)(r0 + row) * HD + c4);
    }
    __syncthreads();
    mm8x4<32, 132, 68>(As, Bs, acc2, tx, ty);
    __syncthreads();
  }

  // ---- main E@V sweep; write normalized attn back ----
  for (int j0 = 0; j0 < S_LEN; j0 += 32) {
#pragma unroll
    for (int l = 0; l < 4; l++) {
      int idx = tid + 256 * l;
      int row = idx >> 3, c4 = (idx & 7) << 2;
      float* Erow = attn + (size_t)(bhS + i0 + row) * S_LEN;
      float4 v = *(const float4*)(Erow + j0 + c4);
      float inv = invs[row];
      *(float4*)(Erow + j0 + c4) =
          make_float4(v.x * inv, v.y * inv, v.z * inv, v.w * inv);
      As[c4 + 0][row] = v.x; As[c4 + 1][row] = v.y;
      As[c4 + 2][row] = v.z; As[c4 + 3][row] = v.w;
    }
#pragma unroll
    for (int l = 0; l < 2; l++) {
      int idx = tid + 256 * l;
      int row = idx >> 4, c4 = (idx & 15) << 2;
      *(float4*)&Bs[row][c4] = *(const float4*)(Vb + (size_t)(j0 + row) * HD + c4);
    }
    __syncthreads();
    mm8x4<32, 132, 68>(As, Bs, acc2, tx, ty);
    __syncthreads();
  }

  float4 ev0 = *(const float4*)(Ev + tx * 4);
  float4 evN = *(const float4*)(Ev + (size_t)(NRPR - 1) * HD + tx * 4);
#pragma unroll
  for (int ip = 0; ip < 4; ip++) {
    float2 f[4];
#pragma unroll
    for (int j = 0; j < 4; j++) f[j] = unpack2(acc2[ip][j]);
#pragma unroll
    for (int rr = 0; rr < 2; rr++) {
      int r = ty * 8 + ip * 2 + rr;
      int i = i0 + r;
      float inv = invs[r], lo = los[r], hi = his[r];
      float o[4];
      o[0] = ((rr ? f[0].y : f[0].x) + lo * ev0.x + hi * evN.x) * inv;
      o[1] = ((rr ? f[1].y : f[1].x) + lo * ev0.y + hi * evN.y) * inv;
      o[2] = ((rr ? f[2].y : f[2].x) + lo * ev0.z + hi * evN.z) * inv;
      o[3] = ((rr ? f[3].y : f[3].x) + lo * ev0.w + hi * evN.w) * inv;
      *(float4*)(g_SC + (size_t)(bhS + i) * HD + tx * 4) =
          make_float4(o[0], o[1], o[2], o[3]);
    }
  }
}

// =====================================================================
// K5: out = concat(scores) @ Wo + bo
// =====================================================================
__global__ void __launch_bounds__(256, 2) out_kernel(const float* __restrict__ Wo,
                                                     const float* __restrict__ bo,
                                                     float* __restrict__ out) {
  __shared__ __align__(16) float As[16][132];
  __shared__ __align__(16) float Bs[16][132];
  const int tid = threadIdx.x;
  const int tx = tid & 15, ty = tid >> 4;
  const int m0 = blockIdx.y * 128;
  const int n0 = blockIdx.x * 128;

  ull acc2[4][8];
#pragma unroll
  for (int i = 0; i < 4; i++)
#pragma unroll
    for (int j = 0; j < 8; j++) acc2[i][j] = 0ull;

  for (int k0 = 0; k0 < DM; k0 += 16) {
#pragma unroll
    for (int l = 0; l < 2; l++) {
      int idx = tid + 256 * l;
      int row = idx >> 2, c4 = (idx & 3) << 2;
      int bs = m0 + row;
      int b = bs >> 11, s = bs & (S_LEN - 1);
      int c = k0 + c4;
      const float* src =
          g_SC + (((size_t)(b * HEADS + (c >> 6))) * S_LEN + s) * HD + (c & 63);
      float4 v = *(const float4*)src;
      As[c4 + 0][row] = v.x; As[c4 + 1][row] = v.y;
      As[c4 + 2][row] = v.z; As[c4 + 3][row] = v.w;
      int br = idx >> 5, bc = (idx & 31) << 2;
      *(float4*)&Bs[br][bc] = *(const float4*)(Wo + (size_t)(k0 + br) * DM + n0 + bc);
    }
    __syncthreads();
    mm8x8<16, 132, 132>(As, Bs, acc2, tx, ty);
    __syncthreads();
  }
  float4 bo0 = *(const float4*)(bo + n0 + tx * 8);
  float4 bo1 = *(const float4*)(bo + n0 + tx * 8 + 4);
#pragma unroll
  for (int ip = 0; ip < 4; ip++) {
    float2 f[8];
#pragma unroll
    for (int j = 0; j < 8; j++) f[j] = unpack2(acc2[ip][j]);
#pragma unroll
    for (int rr = 0; rr < 2; rr++) {
      int row = m0 + ty * 8 + ip * 2 + rr;
      float* dst = out + (size_t)row * DM + n0 + tx * 8;
      float o[8];
#pragma unroll
      for (int j = 0; j < 8; j++) o[j] = rr ? f[j].y : f[j].x;
      *(float4*)&dst[0] = make_float4(o[0] + bo0.x, o[1] + bo0.y, o[2] + bo0.z, o[3] + bo0.w);
      *(float4*)&dst[4] = make_float4(o[4] + bo1.x, o[5] + bo1.y, o[6] + bo1.z, o[7] + bo1.w);
    }
  }
}

// =====================================================================
extern "C" void kernel_launch(void* const* d_in, const int* in_sizes, int n_in,
                              void* d_out, int out_size) {
  const float* query = (const float*)d_in[0];
  const float* value = (const float*)d_in[1];
  const float* Wq    = (const float*)d_in[2];
  const float* Wk    = (const float*)d_in[3];
  const float* Wv    = (const float*)d_in[4];
  const float* Wo    = (const float*)d_in[5];
  const float* bo    = (const float*)d_in[6];
  const float* Ek    = (const float*)d_in[7];
  const float* Ev    = (const float*)d_in[8];

  float* out  = (float*)d_out;                       // (B,S,DM)
  float* attn = out + (size_t)B_SZ * S_LEN * DM;     // (B,H,S,S)

  zero_kernel <<<96, 1024>>>();
  proj_kernel <<<dim3(4, 32, 3),   256>>>(query, value, Wq, Wk, Wv);
  p_kernel    <<<dim3(5, 16, BH),  256>>>(Ek);
  alpha_kernel<<<dim3(16, 16, BH), 256>>>(attn);
  av_kernel   <<<dim3(16, BH),     256>>>(attn, Ev);
  out_kernel  <<<dim3(4, 32),      256>>>(Wo, bo, out);
}